// round 12
// baseline (speedup 1.0000x reference)
#include <cuda_runtime.h>

// Problem constants
#define BN    4096
#define NFEAT 1024
#define RR    64
#define KK    32
#define DD    16

// Tiling
#define BT      8       // b rows per tile
#define RG      16      // regions per block
#define NCONS   256     // consumer threads (8 warps)
#define NPROD   64      // producer threads (2 warps)
#define THREADS (NCONS + NPROD)
#define GRIDX   74      // 74 x 4 groups = 296 blocks = 2 per SM
#define NTILES  (BN / BT)   // 512 b-tiles

#define XPITCH 1028     // smem pitch for raw x rows (bank-decorrelated gather)
#define GPITCH 132      // smem pitch per region for gathered tile [d][b]

// Named barrier ids
#define BAR_FULL0  1
#define BAR_FULL1  2
#define BAR_EMPTY0 3
#define BAR_EMPTY1 4
#define BAR_PROD   5

#define LOG_2PI_F 1.8378770664093453f

typedef unsigned long long u64;

__device__ __forceinline__ u64 ffma2(u64 a, u64 b, u64 c) {
    u64 d;
    asm("fma.rn.f32x2 %0, %1, %2, %3;" : "=l"(d) : "l"(a), "l"(b), "l"(c));
    return d;
}
__device__ __forceinline__ u64 bcast2(float v) {
    u64 d;
    unsigned int r = __float_as_uint(v);
    asm("mov.b64 %0, {%1, %1};" : "=l"(d) : "r"(r));
    return d;
}
__device__ __forceinline__ void unpack2(u64 v, float& lo, float& hi) {
    unsigned int a, b;
    asm("mov.b64 {%0, %1}, %2;" : "=r"(a), "=r"(b) : "l"(v));
    lo = __uint_as_float(a);
    hi = __uint_as_float(b);
}
__device__ __forceinline__ unsigned int smem_u32(const void* p) {
    unsigned int a;
    asm("{ .reg .u64 t; cvta.to.shared.u64 t, %1; cvt.u32.u64 %0, t; }"
        : "=r"(a) : "l"(p));
    return a;
}
__device__ __forceinline__ void bar_sync(int id, int cnt) {
    asm volatile("bar.sync %0, %1;" :: "r"(id), "r"(cnt) : "memory");
}
__device__ __forceinline__ void bar_arrive(int id, int cnt) {
    asm volatile("bar.arrive %0, %1;" :: "r"(id), "r"(cnt) : "memory");
}

// Precomputed parameters (device globals: no allocation allowed)
__device__ float g_wa[RR * DD * KK];   // [r][d][k] = 1/scale
__device__ float g_wb[RR * DD * KK];   // [r][d][k] = -mean/scale
__device__ float g_c [RR * KK];        // [r][k]
__device__ int   g_idx[RR * DD];       // region indices as int32

// ---------------------------------------------------------------------------
// Prep kernel: 64 blocks (one per region) x 512 threads.
// ---------------------------------------------------------------------------
__global__ void prep_kernel(const float* __restrict__ means,
                            const float* __restrict__ scales,
                            const void*  __restrict__ regions_raw) {
    const int r = blockIdx.x;
    const int t = threadIdx.x;       // 0..511
    const int k = t >> 4;
    const int d = t & 15;

    const float s   = scales[((size_t)r * KK + k) * DD + d];
    const float m   = means [((size_t)r * KK + k) * DD + d];
    const float inv = 1.0f / s;
    g_wa[(r * DD + d) * KK + k] = inv;
    g_wb[(r * DD + d) * KK + k] = -m * inv;

    float lg = logf(s);
#pragma unroll
    for (int o = 8; o >= 1; o >>= 1)
        lg += __shfl_xor_sync(0xffffffffu, lg, o);
    if (d == 0)
        g_c[r * KK + k] = -lg - 0.5f * (float)DD * LOG_2PI_F;

    if (r == 0) {
        // int64 detection: if regions is int64 (values < 1024), every odd
        // 32-bit word is zero.
        __shared__ int s_or;
        if (t == 0) s_or = 0;
        __syncthreads();
        const int* w = (const int*)regions_raw;
        int v = w[2 * t + 1];
#pragma unroll
        for (int o = 16; o >= 1; o >>= 1)
            v |= __shfl_xor_sync(0xffffffffu, v, o);
        if ((t & 31) == 0) atomicOr(&s_or, v);
        __syncthreads();
        const int is64 = (s_or == 0);
        g_idx[2 * t]     = is64 ? w[4 * t]     : w[2 * t];
        g_idx[2 * t + 1] = is64 ? w[4 * t + 2] : w[2 * t + 1];
    }
}

// ---------------------------------------------------------------------------
// Main kernel: warp-specialized persistent blocks, grid (74, 4) = 2/SM.
// 320 threads: 256 consumers (compute only) + 64 producers (load + gather).
// Double-buffered xg; named-barrier handshake; consumers have NO barriers
// except the full/empty rendezvous and NO memory ops except LDS + STG.
// ---------------------------------------------------------------------------
__global__ __launch_bounds__(THREADS, 2)
void main_kernel(const float* __restrict__ x, float* __restrict__ out) {
    extern __shared__ float smem[];
    float* sm_x0  = smem;                             // BT*XPITCH
    float* sm_x1  = smem + BT * XPITCH;
    float* sm_g0  = smem + 2 * BT * XPITCH;           // RG*GPITCH
    float* sm_g1  = sm_g0 + RG * GPITCH;
    int*   sm_idx = (int*)(sm_g1 + RG * GPITCH);      // RG*DD = 256

    const int tid = threadIdx.x;
    const int r0  = blockIdx.y * RG;
    const int t0  = blockIdx.x;

    if (tid < 256) sm_idx[tid] = g_idx[r0 * DD + tid];

    if (tid >= NCONS) {
        // =================== PRODUCER (2 warps) ===================
        const int p = tid - NCONS;          // 0..63
        const unsigned int s_x[2] = { smem_u32(sm_x0), smem_u32(sm_x1) };
        float* const sm_g[2] = { sm_g0, sm_g1 };
        const float* const sm_xb[2] = { sm_x0, sm_x1 };

        // Prologue: issue load of tile t0 into sm_x[0]
        {
            const float* xrow = x + (size_t)t0 * BT * NFEAT;
#pragma unroll
            for (int i = p; i < BT * (NFEAT / 4); i += NPROD) {
                const int row = i >> 8;
                const int c   = i & 255;
                const unsigned int dst =
                    s_x[0] + (unsigned)(row * XPITCH + c * 4) * 4u;
                asm volatile("cp.async.cg.shared.global [%0], [%1], 16;"
                             :: "r"(dst), "l"(xrow + (size_t)row * NFEAT + c * 4));
            }
            asm volatile("cp.async.commit_group;" ::: "memory");
        }
        __syncthreads();   // sm_idx visible

        for (int j = 0, t = t0; t < NTILES; j++, t += GRIDX) {
            const int xb = j & 1;
            // Wait this warp's loads; then producer-bar so BOTH producer
            // warps' loads for tile t are complete.
            asm volatile("cp.async.wait_group 0;" ::: "memory");
            bar_sync(BAR_PROD, NPROD);

            // Issue load of tile t+G into the other x buffer (its last
            // reader, gather(j-1), finished before this thread's bar).
            const int tf = t + GRIDX;
            if (tf < NTILES) {
                const float* xrow = x + (size_t)tf * BT * NFEAT;
#pragma unroll
                for (int i = p; i < BT * (NFEAT / 4); i += NPROD) {
                    const int row = i >> 8;
                    const int c   = i & 255;
                    const unsigned int dst =
                        s_x[xb ^ 1] + (unsigned)(row * XPITCH + c * 4) * 4u;
                    asm volatile("cp.async.cg.shared.global [%0], [%1], 16;"
                                 :: "r"(dst), "l"(xrow + (size_t)row * NFEAT + c * 4));
                }
            }
            asm volatile("cp.async.commit_group;" ::: "memory");

            // Wait until consumers are done with xg[xb] (tile t-2).
            if (j >= 2) bar_sync(BAR_EMPTY0 + xb, THREADS);

            // Gather tile t: sm_x[xb] -> xg[xb]
            const float* src = sm_xb[xb];
            float* dst = sm_g[xb];
#pragma unroll
            for (int i = 0; i < 32; i++) {
                const int e  = p + i * NPROD;
                const int b  = e & (BT - 1);
                const int d  = (e >> 3) & (DD - 1);
                const int rg = e >> 7;
                dst[rg * GPITCH + d * BT + b] =
                    src[b * XPITCH + sm_idx[rg * DD + d]];
            }
            bar_arrive(BAR_FULL0 + xb, THREADS);
        }
    } else {
        // =================== CONSUMER (8 warps) ===================
        const int rl = tid >> 4;         // region within block: 0..15
        const int kp = tid & 15;         // k-pair: k0 = kp*2
        const int r  = r0 + rl;
        const int k0 = kp * 2;

        // Weights resident (float2 per d per array)
        float2 wa2[DD], wb2[DD];
        {
            const float* wap = g_wa + r * DD * KK + k0;
            const float* wbp = g_wb + r * DD * KK + k0;
#pragma unroll
            for (int d = 0; d < DD; d++) {
                wa2[d] = *(const float2*)(wap + d * KK);
                wb2[d] = *(const float2*)(wbp + d * KK);
            }
        }
        const float2 c2 = *(const float2*)&g_c[r * KK + k0];
        const u64 nh  = bcast2(-0.5f);
        const u64 cc0 = bcast2(c2.x);
        const u64 cc1 = bcast2(c2.y);

        const float* const xg[2] = { sm_g0 + rl * GPITCH, sm_g1 + rl * GPITCH };

        __syncthreads();   // matches producer's syncthreads

        for (int j = 0, t = t0; t < NTILES; j++, t += GRIDX) {
            const int xb = j & 1;
            bar_sync(BAR_FULL0 + xb, THREADS);

            const float* xp = xg[xb];
            u64 acc0[4], acc1[4];
#pragma unroll
            for (int pq = 0; pq < 4; pq++) { acc0[pq] = 0ull; acc1[pq] = 0ull; }

#pragma unroll
            for (int d = 0; d < DD; d++) {
                const ulonglong2 xA = *(const ulonglong2*)(xp + d * BT);
                const ulonglong2 xB = *(const ulonglong2*)(xp + d * BT + 4);
                const u64 xv[4] = {xA.x, xA.y, xB.x, xB.y};
                const u64 aa0 = bcast2(wa2[d].x);
                const u64 aa1 = bcast2(wa2[d].y);
                const u64 bb0 = bcast2(wb2[d].x);
                const u64 bb1 = bcast2(wb2[d].y);
#pragma unroll
                for (int pq = 0; pq < 4; pq++) {
                    const u64 z0 = ffma2(xv[pq], aa0, bb0);
                    acc0[pq] = ffma2(z0, z0, acc0[pq]);
                    const u64 z1 = ffma2(xv[pq], aa1, bb1);
                    acc1[pq] = ffma2(z1, z1, acc1[pq]);
                }
            }
            bar_arrive(BAR_EMPTY0 + xb, THREADS);

            // Epilogue (after releasing the buffer: overlaps producer)
            const int b0 = t * BT;
#pragma unroll
            for (int pq = 0; pq < 4; pq++) {
                const u64 o0 = ffma2(acc0[pq], nh, cc0);
                const u64 o1 = ffma2(acc1[pq], nh, cc1);
                float o0lo, o0hi, o1lo, o1hi;
                unpack2(o0, o0lo, o0hi);
                unpack2(o1, o1lo, o1hi);
                *(float2*)&out[((size_t)(b0 + 2 * pq)     * RR + r) * KK + k0] =
                    make_float2(o0lo, o1lo);
                *(float2*)&out[((size_t)(b0 + 2 * pq + 1) * RR + r) * KK + k0] =
                    make_float2(o0hi, o1hi);
            }
        }
    }
}

// ---------------------------------------------------------------------------
#define SMEM_BYTES ((2 * BT * XPITCH + 2 * RG * GPITCH) * 4 + RG * DD * 4)

extern "C" void kernel_launch(void* const* d_in, const int* in_sizes, int n_in,
                              void* d_out, int out_size) {
    const float* x       = (const float*)d_in[0];
    const void*  regions = d_in[1];                // int64 or int32, detected
    const float* means   = (const float*)d_in[2];
    const float* scales  = (const float*)d_in[3];
    float*       out     = (float*)d_out;

    cudaFuncSetAttribute(main_kernel,
                         cudaFuncAttributeMaxDynamicSharedMemorySize,
                         SMEM_BYTES);

    prep_kernel<<<RR, 512>>>(means, scales, regions);

    dim3 grid(GRIDX, RR / RG);
    main_kernel<<<grid, THREADS, SMEM_BYTES>>>(x, out);
}

// round 13
// speedup vs baseline: 1.3559x; 1.3559x over previous
#include <cuda_runtime.h>

// Problem constants
#define BN    4096
#define NFEAT 1024
#define RR    64
#define KK    32
#define DD    16

// Tiling
#define BT      8       // b rows per tile
#define RG      16      // regions per block
#define THREADS 256
#define GRIDX   74      // 74 x 4 groups = 296 blocks = 2 per SM
#define NTILES  (BN / BT)   // 512 b-tiles
#define DEPTH   3       // cp.async ring depth

#define XPITCH 1028     // smem pitch for raw x rows (bank-decorrelated gather)
#define GPITCH 132      // smem pitch per region for gathered tile [d][b]

#define LOG_2PI_F 1.8378770664093453f

typedef unsigned long long u64;

// Packed fp32x2 helpers (sm_103a FFMA2 — only reachable via PTX)
__device__ __forceinline__ u64 ffma2(u64 a, u64 b, u64 c) {
    u64 d;
    asm("fma.rn.f32x2 %0, %1, %2, %3;" : "=l"(d) : "l"(a), "l"(b), "l"(c));
    return d;
}
__device__ __forceinline__ u64 bcast2(float v) {
    u64 d;
    unsigned int r = __float_as_uint(v);
    asm("mov.b64 %0, {%1, %1};" : "=l"(d) : "r"(r));
    return d;
}
__device__ __forceinline__ void unpack2(u64 v, float& lo, float& hi) {
    unsigned int a, b;
    asm("mov.b64 {%0, %1}, %2;" : "=r"(a), "=r"(b) : "l"(v));
    lo = __uint_as_float(a);
    hi = __uint_as_float(b);
}
__device__ __forceinline__ unsigned int smem_u32(const void* p) {
    unsigned int a;
    asm("{ .reg .u64 t; cvta.to.shared.u64 t, %1; cvt.u32.u64 %0, t; }"
        : "=r"(a) : "l"(p));
    return a;
}

// Precomputed parameters (device globals: no allocation allowed)
__device__ u64   g_wpa[RR * DD * KK];  // [r][d][k] = broadcast2(1/scale)
__device__ u64   g_wpb[RR * DD * KK];  // [r][d][k] = broadcast2(-mean/scale)
__device__ float g_c [RR * KK];        // [r][k]
__device__ int   g_idx[RR * DD];       // region indices as int32

// ---------------------------------------------------------------------------
// Prep kernel: 64 blocks (one per region) x 512 threads.
// Writes PRE-PACKED broadcast u64 weights so the main loop needs no movs.
// ---------------------------------------------------------------------------
__global__ void prep_kernel(const float* __restrict__ means,
                            const float* __restrict__ scales,
                            const void*  __restrict__ regions_raw) {
    const int r = blockIdx.x;
    const int t = threadIdx.x;       // 0..511
    const int k = t >> 4;
    const int d = t & 15;

    const float s   = scales[((size_t)r * KK + k) * DD + d];
    const float m   = means [((size_t)r * KK + k) * DD + d];
    const float inv = 1.0f / s;
    g_wpa[(r * DD + d) * KK + k] = bcast2(inv);
    g_wpb[(r * DD + d) * KK + k] = bcast2(-m * inv);

    float lg = logf(s);
#pragma unroll
    for (int o = 8; o >= 1; o >>= 1)
        lg += __shfl_xor_sync(0xffffffffu, lg, o);
    if (d == 0)
        g_c[r * KK + k] = -lg - 0.5f * (float)DD * LOG_2PI_F;

    if (r == 0) {
        // int64 detection: if regions is int64 (values < 1024), every odd
        // 32-bit word is zero.
        __shared__ int s_or;
        if (t == 0) s_or = 0;
        __syncthreads();
        const int* w = (const int*)regions_raw;
        int v = w[2 * t + 1];
#pragma unroll
        for (int o = 16; o >= 1; o >>= 1)
            v |= __shfl_xor_sync(0xffffffffu, v, o);
        if ((t & 31) == 0) atomicOr(&s_or, v);
        __syncthreads();
        const int is64 = (s_or == 0);
        g_idx[2 * t]     = is64 ? w[4 * t]     : w[2 * t];
        g_idx[2 * t + 1] = is64 ? w[4 * t + 2] : w[2 * t + 1];
    }
}

// ---------------------------------------------------------------------------
// Main kernel: persistent blocks, grid = (74, 4) = 296 = 2 blocks/SM.
// Block (bx, g): r-group g (16 regions), b-tiles t = bx + j*74.
// ONE block barrier per tile: each warp gathers ONLY its own two regions
// (the ones its lanes consume), so gather->compute needs just __syncwarp
// and warps overlap freely across the gather/compute/epilogue region.
// 3-deep cp.async ring; refill issued after compute (buffer last read by
// gather(j-1), retired by barrier(j)). Weights pre-packed u64, resident.
// ---------------------------------------------------------------------------
__global__ __launch_bounds__(THREADS, 2)
void main_kernel(const float* __restrict__ x, float* __restrict__ out) {
    extern __shared__ float smem[];
    float* sm_xb[DEPTH];
    sm_xb[0] = smem;
    sm_xb[1] = smem + BT * XPITCH;
    sm_xb[2] = smem + 2 * BT * XPITCH;
    float* sm_xg  = smem + DEPTH * BT * XPITCH;   // RG*GPITCH
    int*   sm_idx = (int*)(sm_xg + RG * GPITCH);  // RG*DD = 256

    const int tid  = threadIdx.x;
    const int r0   = blockIdx.y * RG;
    const int w    = tid >> 5;        // warp: 0..7, owns regions 2w, 2w+1
    const int lane = tid & 31;

    const int rl = tid >> 4;          // consumed region: 0..15
    const int kp = tid & 15;          // k-pair: k0 = kp*2
    const int r  = r0 + rl;
    const int k0 = kp * 2;

    // ---- One-time: indices to smem; packed weights to registers ----
    sm_idx[tid] = g_idx[r0 * DD + tid];           // 256 == RG*DD

    ulonglong2 wab[DD], wbb[DD];   // .x = k0 bcast, .y = k0+1 bcast
    {
        const u64* wap = g_wpa + (size_t)r * DD * KK + k0;
        const u64* wbp = g_wpb + (size_t)r * DD * KK + k0;
#pragma unroll
        for (int d = 0; d < DD; d++) {
            wab[d] = *(const ulonglong2*)(wap + d * KK);
            wbb[d] = *(const ulonglong2*)(wbp + d * KK);
        }
    }
    const float2 c2 = *(const float2*)&g_c[r * KK + k0];
    const u64 nh  = bcast2(-0.5f);
    const u64 cc0 = bcast2(c2.x);
    const u64 cc1 = bcast2(c2.y);

    unsigned int s_xb[DEPTH];
#pragma unroll
    for (int p = 0; p < DEPTH; p++) s_xb[p] = smem_u32(sm_xb[p]);

    // ---- Prologue: issue loads for tiles t0, t0+G into bufs 0, 1 ----
    const int t0 = blockIdx.x;
#pragma unroll
    for (int p = 0; p < DEPTH - 1; p++) {
        const int tp = t0 + p * GRIDX;
        if (tp < NTILES) {
            const float* xrow = x + (size_t)tp * BT * NFEAT;
#pragma unroll
            for (int i = tid; i < BT * (NFEAT / 4); i += THREADS) {
                const int row = i >> 8;
                const int c   = i & 255;
                const unsigned int dst =
                    s_xb[p] + (unsigned)(row * XPITCH + c * 4) * 4u;
                asm volatile("cp.async.cg.shared.global [%0], [%1], 16;"
                             :: "r"(dst), "l"(xrow + (size_t)row * NFEAT + c * 4));
            }
        }
        asm volatile("cp.async.commit_group;" ::: "memory");
    }

    // Warp's gather targets: regions 2w, 2w+1
    const int rbase = 2 * w;
    float* const xg0 = sm_xg + rbase * GPITCH;

    // ---- Pipelined tile loop: ONE barrier per tile ----
    int bufj = 0;
    for (int j = 0, t = t0; t < NTILES; j++, t += GRIDX) {
        // Own groups for tile t complete (issued 2 iterations back);
        // barrier makes ALL threads' loads visible and retires gather(j-1).
        asm volatile("cp.async.wait_group 1;" ::: "memory");
        __syncthreads();

        // ---- Warp-local gather of regions 2w, 2w+1 ----
        const float* sm_cur = sm_xb[bufj];
#pragma unroll
        for (int i = 0; i < 8; i++) {
            const int e   = lane + 32 * i;       // 0..255
            const int b   = e & (BT - 1);
            const int d   = (e >> 3) & (DD - 1);
            const int rgl = e >> 7;              // 0 or 1
            const int col = sm_idx[(rbase + rgl) * DD + d];
            xg0[rgl * GPITCH + d * BT + b] = sm_cur[b * XPITCH + col];
        }
        __syncwarp();

        // ---- Compute: per d, 2 LDS.128 (broadcast) + 16 FFMA2, no movs ----
        const float* xp = sm_xg + rl * GPITCH;

        u64 acc0[4], acc1[4];
#pragma unroll
        for (int p = 0; p < 4; p++) { acc0[p] = 0ull; acc1[p] = 0ull; }

#pragma unroll
        for (int d = 0; d < DD; d++) {
            const ulonglong2 xA = *(const ulonglong2*)(xp + d * BT);
            const ulonglong2 xB = *(const ulonglong2*)(xp + d * BT + 4);
            const u64 xv[4] = {xA.x, xA.y, xB.x, xB.y};
            const u64 aa0 = wab[d].x, aa1 = wab[d].y;
            const u64 bb0 = wbb[d].x, bb1 = wbb[d].y;
#pragma unroll
            for (int p = 0; p < 4; p++) {
                const u64 z0 = ffma2(xv[p], aa0, bb0);
                acc0[p] = ffma2(z0, z0, acc0[p]);
                const u64 z1 = ffma2(xv[p], aa1, bb1);
                acc1[p] = ffma2(z1, z1, acc1[p]);
            }
        }

        // ---- Epilogue: out[b][r][k0..k0+1] = -0.5*acc + C ----
        const int b0 = t * BT;
#pragma unroll
        for (int p = 0; p < 4; p++) {
            const u64 o0 = ffma2(acc0[p], nh, cc0);
            const u64 o1 = ffma2(acc1[p], nh, cc1);
            float o0lo, o0hi, o1lo, o1hi;
            unpack2(o0, o0lo, o0hi);
            unpack2(o1, o1lo, o1hi);
            *(float2*)&out[((size_t)(b0 + 2 * p)     * RR + r) * KK + k0] =
                make_float2(o0lo, o1lo);
            *(float2*)&out[((size_t)(b0 + 2 * p + 1) * RR + r) * KK + k0] =
                make_float2(o0hi, o1hi);
        }

        // ---- Refill: tile t+2G into buf (bufj+2)%3 (safe: its last
        //      reader was gather(j-1), retired by this iter's barrier) ----
        const int tf = t + (DEPTH - 1) * GRIDX;
        int buff = bufj + 2; if (buff >= DEPTH) buff -= DEPTH;
        if (tf < NTILES) {
            const float* xrow = x + (size_t)tf * BT * NFEAT;
#pragma unroll
            for (int i = tid; i < BT * (NFEAT / 4); i += THREADS) {
                const int row = i >> 8;
                const int c   = i & 255;
                const unsigned int dst =
                    s_xb[buff] + (unsigned)(row * XPITCH + c * 4) * 4u;
                asm volatile("cp.async.cg.shared.global [%0], [%1], 16;"
                             :: "r"(dst), "l"(xrow + (size_t)row * NFEAT + c * 4));
            }
        }
        asm volatile("cp.async.commit_group;" ::: "memory");

        if (++bufj == DEPTH) bufj = 0;
    }
}

// ---------------------------------------------------------------------------
#define SMEM_BYTES ((DEPTH * BT * XPITCH + RG * GPITCH) * 4 + RG * DD * 4)

extern "C" void kernel_launch(void* const* d_in, const int* in_sizes, int n_in,
                              void* d_out, int out_size) {
    const float* x       = (const float*)d_in[0];
    const void*  regions = d_in[1];                // int64 or int32, detected
    const float* means   = (const float*)d_in[2];
    const float* scales  = (const float*)d_in[3];
    float*       out     = (float*)d_out;

    cudaFuncSetAttribute(main_kernel,
                         cudaFuncAttributeMaxDynamicSharedMemorySize,
                         SMEM_BYTES);

    prep_kernel<<<RR, 512>>>(means, scales, regions);

    dim3 grid(GRIDX, RR / RG);
    main_kernel<<<grid, THREADS, SMEM_BYTES>>>(x, out);
}

// round 14
// speedup vs baseline: 2.1429x; 1.5804x over previous
#include <cuda_runtime.h>

// Problem constants
#define BN    4096
#define NFEAT 1024
#define RR    64
#define KK    32
#define DD    16

// Tiling
#define BT      8       // b rows per tile
#define RG      16      // regions per block
#define THREADS 256
#define GRIDX   74      // 74 x 4 groups = 296 blocks = 2 per SM
#define NTILES  (BN / BT)   // 512 b-tiles

#define XPITCH 1028     // smem pitch for raw x rows (bank-decorrelated gather)
#define GPITCH 132      // smem pitch per region for gathered tile [d][b]

#define LOG_2PI_F 1.8378770664093453f

typedef unsigned long long u64;

// Packed fp32x2 helpers (sm_103a FFMA2 — only reachable via PTX)
__device__ __forceinline__ u64 ffma2(u64 a, u64 b, u64 c) {
    u64 d;
    asm("fma.rn.f32x2 %0, %1, %2, %3;" : "=l"(d) : "l"(a), "l"(b), "l"(c));
    return d;
}
__device__ __forceinline__ u64 bcast2(float v) {
    u64 d;
    unsigned int r = __float_as_uint(v);
    asm("mov.b64 %0, {%1, %1};" : "=l"(d) : "r"(r));
    return d;
}
__device__ __forceinline__ void unpack2(u64 v, float& lo, float& hi) {
    unsigned int a, b;
    asm("mov.b64 {%0, %1}, %2;" : "=r"(a), "=r"(b) : "l"(v));
    lo = __uint_as_float(a);
    hi = __uint_as_float(b);
}
__device__ __forceinline__ unsigned int smem_u32(const void* p) {
    unsigned int a;
    asm("{ .reg .u64 t; cvta.to.shared.u64 t, %1; cvt.u32.u64 %0, t; }"
        : "=r"(a) : "l"(p));
    return a;
}

// Precomputed parameters (device globals: no allocation allowed)
__device__ float g_wa[RR * DD * KK];   // [r][d][k] = 1/scale
__device__ float g_wb[RR * DD * KK];   // [r][d][k] = -mean/scale
__device__ float g_c [RR * KK];        // [r][k]
__device__ int   g_idx[RR * DD];       // region indices as int32

// ---------------------------------------------------------------------------
// Prep kernel: 64 blocks (one per region) x 512 threads.
// ---------------------------------------------------------------------------
__global__ void prep_kernel(const float* __restrict__ means,
                            const float* __restrict__ scales,
                            const void*  __restrict__ regions_raw) {
    const int r = blockIdx.x;
    const int t = threadIdx.x;       // 0..511
    const int k = t >> 4;
    const int d = t & 15;

    const float s   = scales[((size_t)r * KK + k) * DD + d];
    const float m   = means [((size_t)r * KK + k) * DD + d];
    const float inv = 1.0f / s;
    g_wa[(r * DD + d) * KK + k] = inv;
    g_wb[(r * DD + d) * KK + k] = -m * inv;

    float lg = logf(s);
#pragma unroll
    for (int o = 8; o >= 1; o >>= 1)
        lg += __shfl_xor_sync(0xffffffffu, lg, o);
    if (d == 0)
        g_c[r * KK + k] = -lg - 0.5f * (float)DD * LOG_2PI_F;

    if (r == 0) {
        // int64 detection: if regions is int64 (values < 1024), every odd
        // 32-bit word is zero.
        __shared__ int s_or;
        if (t == 0) s_or = 0;
        __syncthreads();
        const int* w = (const int*)regions_raw;
        int v = w[2 * t + 1];
#pragma unroll
        for (int o = 16; o >= 1; o >>= 1)
            v |= __shfl_xor_sync(0xffffffffu, v, o);
        if ((t & 31) == 0) atomicOr(&s_or, v);
        __syncthreads();
        const int is64 = (s_or == 0);
        g_idx[2 * t]     = is64 ? w[4 * t]     : w[2 * t];
        g_idx[2 * t + 1] = is64 ? w[4 * t + 2] : w[2 * t + 1];
    }
}

// ---------------------------------------------------------------------------
// Main kernel: persistent blocks, grid = (74, 4) = 296 = 2 blocks/SM.
// Identical to the proven round-6 kernel EXCEPT the sync topology:
//  - sm_xg is warp-private (warp w gathers and consumes regions 2w, 2w+1)
//  - ONE __syncthreads per tile (x-buffer handoff); gather->compute is
//    ordered by __syncwarp only, so warps drift and overlap phases
//  - double-buffered cp.async; load(j+1) issued after this warp's gather(j)
//    (target buffer's last reader was gather(j-1), retired at barrier(j))
// ---------------------------------------------------------------------------
__global__ __launch_bounds__(THREADS, 2)
void main_kernel(const float* __restrict__ x, float* __restrict__ out) {
    extern __shared__ float smem[];
    float* sm_x0  = smem;                         // BT*XPITCH
    float* sm_x1  = smem + BT * XPITCH;           // BT*XPITCH
    float* sm_xg  = smem + 2 * BT * XPITCH;       // RG*GPITCH
    int*   sm_idx = (int*)(sm_xg + RG * GPITCH);  // RG*DD = 256

    const int tid  = threadIdx.x;
    const int r0   = blockIdx.y * RG;
    const int w    = tid >> 5;        // warp: 0..7 owns regions 2w, 2w+1
    const int lane = tid & 31;

    const int rl = tid >> 4;          // consumed region: 0..15
    const int kp = tid & 15;          // k-pair: k0 = kp*2
    const int r  = r0 + rl;
    const int k0 = kp * 2;

    // ---- One-time: gather indices to smem; weights to registers ----
    sm_idx[tid] = g_idx[r0 * DD + tid];           // 256 == RG*DD

    float2 wa2[DD], wb2[DD];
    {
        const float* wap = g_wa + r * DD * KK + k0;
        const float* wbp = g_wb + r * DD * KK + k0;
#pragma unroll
        for (int d = 0; d < DD; d++) {
            wa2[d] = *(const float2*)(wap + d * KK);
            wb2[d] = *(const float2*)(wbp + d * KK);
        }
    }
    const float2 c2 = *(const float2*)&g_c[r * KK + k0];

    const unsigned int s_x0 = smem_u32(sm_x0);
    const unsigned int s_x1 = smem_u32(sm_x1);

    // Warp-local gather targets: regions 2w, 2w+1
    const int rbase = 2 * w;
    float* const xg0 = sm_xg + rbase * GPITCH;

    // ---- Prologue: issue load of first tile into buf0 ----
    const int t0 = blockIdx.x;
    {
        const float* xrow = x + (size_t)t0 * BT * NFEAT;
#pragma unroll
        for (int i = tid; i < BT * (NFEAT / 4); i += THREADS) {
            const int row = i >> 8;
            const int c   = i & 255;
            const unsigned int dst = s_x0 + (unsigned)(row * XPITCH + c * 4) * 4u;
            asm volatile("cp.async.cg.shared.global [%0], [%1], 16;"
                         :: "r"(dst), "l"(xrow + (size_t)row * NFEAT + c * 4));
        }
        asm volatile("cp.async.commit_group;" ::: "memory");
    }

    // ---- Pipelined tile loop: ONE block barrier per tile ----
    for (int j = 0, t = t0; t < NTILES; j++, t += GRIDX) {
        // Load(j) complete; gather(j-1) retired by every warp.
        asm volatile("cp.async.wait_group 0;" ::: "memory");
        __syncthreads();

        // ---- Warp-local gather of regions 2w, 2w+1 from buf j&1 ----
        const float* sm_cur = (j & 1) ? sm_x1 : sm_x0;
#pragma unroll
        for (int i = 0; i < 8; i++) {
            const int e   = lane + 32 * i;       // 0..255
            const int b   = e & (BT - 1);
            const int d   = (e >> 3) & (DD - 1);
            const int rgl = e >> 7;              // 0 or 1
            const int col = sm_idx[(rbase + rgl) * DD + d];
            xg0[rgl * GPITCH + d * BT + b] = sm_cur[b * XPITCH + col];
        }
        __syncwarp();

        // ---- Issue load(j+1) into the other buffer (safe: last reader
        //      gather(j-1) retired at this tile's barrier) ----
        const int tf = t + GRIDX;
        if (tf < NTILES) {
            const unsigned int s_nxt = (j & 1) ? s_x0 : s_x1;
            const float* xrow = x + (size_t)tf * BT * NFEAT;
#pragma unroll
            for (int i = tid; i < BT * (NFEAT / 4); i += THREADS) {
                const int row = i >> 8;
                const int c   = i & 255;
                const unsigned int dst =
                    s_nxt + (unsigned)(row * XPITCH + c * 4) * 4u;
                asm volatile("cp.async.cg.shared.global [%0], [%1], 16;"
                             :: "r"(dst), "l"(xrow + (size_t)row * NFEAT + c * 4));
            }
        }
        asm volatile("cp.async.commit_group;" ::: "memory");

        // ---- Compute (warp-private xg): 2 LDS.128 + 4 mov + 16 FFMA2 per d
        const float* xp = sm_xg + rl * GPITCH;

        u64 acc0[4], acc1[4];
#pragma unroll
        for (int p = 0; p < 4; p++) { acc0[p] = 0ull; acc1[p] = 0ull; }

#pragma unroll
        for (int d = 0; d < DD; d++) {
            const ulonglong2 xA = *(const ulonglong2*)(xp + d * BT);
            const ulonglong2 xB = *(const ulonglong2*)(xp + d * BT + 4);
            const u64 xv[4] = {xA.x, xA.y, xB.x, xB.y};

            const u64 aa0 = bcast2(wa2[d].x);
            const u64 aa1 = bcast2(wa2[d].y);
            const u64 bb0 = bcast2(wb2[d].x);
            const u64 bb1 = bcast2(wb2[d].y);
#pragma unroll
            for (int p = 0; p < 4; p++) {
                const u64 z0 = ffma2(xv[p], aa0, bb0);
                acc0[p] = ffma2(z0, z0, acc0[p]);
                const u64 z1 = ffma2(xv[p], aa1, bb1);
                acc1[p] = ffma2(z1, z1, acc1[p]);
            }
        }

        // ---- Epilogue: out[b][r][k0..k0+1] = -0.5*acc + C ----
        const int b0 = t * BT;
        const u64 nh  = bcast2(-0.5f);
        const u64 cc0 = bcast2(c2.x);
        const u64 cc1 = bcast2(c2.y);
#pragma unroll
        for (int p = 0; p < 4; p++) {
            const u64 o0 = ffma2(acc0[p], nh, cc0);
            const u64 o1 = ffma2(acc1[p], nh, cc1);
            float o0lo, o0hi, o1lo, o1hi;
            unpack2(o0, o0lo, o0hi);
            unpack2(o1, o1lo, o1hi);
            *(float2*)&out[((size_t)(b0 + 2 * p)     * RR + r) * KK + k0] =
                make_float2(o0lo, o1lo);
            *(float2*)&out[((size_t)(b0 + 2 * p + 1) * RR + r) * KK + k0] =
                make_float2(o0hi, o1hi);
        }
    }
}

// ---------------------------------------------------------------------------
#define SMEM_BYTES ((2 * BT * XPITCH + RG * GPITCH) * 4 + RG * DD * 4)

extern "C" void kernel_launch(void* const* d_in, const int* in_sizes, int n_in,
                              void* d_out, int out_size) {
    const float* x       = (const float*)d_in[0];
    const void*  regions = d_in[1];                // int64 or int32, detected
    const float* means   = (const float*)d_in[2];
    const float* scales  = (const float*)d_in[3];
    float*       out     = (float*)d_out;

    cudaFuncSetAttribute(main_kernel,
                         cudaFuncAttributeMaxDynamicSharedMemorySize,
                         SMEM_BYTES);

    prep_kernel<<<RR, 512>>>(means, scales, regions);

    dim3 grid(GRIDX, RR / RG);
    main_kernel<<<grid, THREADS, SMEM_BYTES>>>(x, out);
}